// round 13
// baseline (speedup 1.0000x reference)
#include <cuda_runtime.h>
#include <cuda_fp16.h>
#include <cstdint>
#include <math.h>

#define V_  32000
#define E_  128
#define L_  2
#define B_  32
#define T_  128
#define G_  512          // 4*E
#define BT_ (B_*T_)      // 4096

// ---------------- device scratch (no allocations allowed) ----------------
__device__ __half g_x16 [BT_*E_];   // embedded inputs, fp16
__device__ __half g_h016[BT_*E_];   // layer-0 hidden seq, fp16 (feeds L1 gemm)
__device__ __half g_Ah  [BT_*E_];   // layer-1 hidden seq, fp16 (feeds proj)
__device__ float  g_xh [BT_*G_];    // x @ Wx for current layer (8 MB)
__device__ __half g_Wx16[L_*E_*G_]; // fp16 copy of Wx
__device__ __half g_W16 [V_*E_];    // fp16 copy of softmax_w (8 MB)

__device__ __forceinline__ uint32_t s2u(const void* p)
{
    uint32_t a;
    asm("{ .reg .u64 t; cvta.to.shared.u64 t, %1; cvt.u32.u64 %0, t; }"
        : "=r"(a) : "l"(p));
    return a;
}

// ---------------- fast transcendentals (ex2/rcp approx, rel err ~1e-6) ----
__device__ __forceinline__ float sigm(float x)
{
    float e; asm("ex2.approx.ftz.f32 %0, %1;" : "=f"(e) : "f"(-1.4426950408889634f * x));
    float r; asm("rcp.approx.ftz.f32 %0, %1;" : "=f"(r) : "f"(1.0f + e));
    return r;
}
__device__ __forceinline__ float ftanh(float x)
{
    x = fmaxf(x, -40.0f);          // guard ex2 overflow -> NaN
    float e; asm("ex2.approx.ftz.f32 %0, %1;" : "=f"(e) : "f"(-2.8853900817779268f * x));
    float r; asm("rcp.approx.ftz.f32 %0, %1;" : "=f"(r) : "f"(1.0f + e));
    return (1.0f - e) * r;
}

// ---------------- embedding gather (emit fp16) ----------------
__global__ void k_embed(const int* __restrict__ ids, const float* __restrict__ emb)
{
    int idx = blockIdx.x * blockDim.x + threadIdx.x;
    if (idx < BT_*E_) {
        int row = idx >> 7;
        int e   = idx & 127;
        g_x16[idx] = __float2half(emb[(size_t)ids[row]*E_ + e]);
    }
}

// ---------------- fp32 -> fp16 weight converts ----------------
__global__ void k_w2half(const float* __restrict__ w)
{
    int idx = blockIdx.x * blockDim.x + threadIdx.x;
    if (idx < V_*E_) g_W16[idx] = __float2half(w[idx]);
}
__global__ void k_wx2half(const float* __restrict__ wx)
{
    int idx = blockIdx.x * blockDim.x + threadIdx.x;
    if (idx < L_*E_*G_) g_Wx16[idx] = __float2half(wx[idx]);
}

// ---------------- HMMA helper ----------------
__device__ __forceinline__ void mma16816(float* c, const uint32_t* a,
                                         uint32_t b0, uint32_t b1)
{
    asm volatile(
        "mma.sync.aligned.m16n8k16.row.col.f32.f16.f16.f32 "
        "{%0,%1,%2,%3}, {%4,%5,%6,%7}, {%8,%9}, {%0,%1,%2,%3};\n"
        : "+f"(c[0]), "+f"(c[1]), "+f"(c[2]), "+f"(c[3])
        : "r"(a[0]), "r"(a[1]), "r"(a[2]), "r"(a[3]), "r"(b0), "r"(b1));
}

#define SA_ 136   // padded smem row in halves

// ---------------- xh GEMM (fp16 HMMA): (BT x E) @ (E x G) -> g_xh ----------------
__global__ void __launch_bounds__(256, 2)
k_gemm_xh(int layer, int src)
{
    const __half* A    = src ? g_h016 : g_x16;
    const __half* Wx16 = g_Wx16 + (size_t)layer * E_ * G_;
    extern __shared__ __half gsm[];
    __half* As = gsm;              // [64][SA_]
    __half* Bs = gsm + 64*SA_;     // [64][SA_]  (n-major, k contiguous)

    const int tid  = threadIdx.x;
    const int wid  = tid >> 5, lane = tid & 31;
    const int gid  = lane >> 2, tig = lane & 3;
    const int wm   = wid >> 2, wn = wid & 3;      // 2 x 4 warps
    const int rb   = blockIdx.y * 64;
    const int nb   = blockIdx.x * 64;

    #pragma unroll
    for (int i = tid; i < 1024; i += 256) {
        int r = i >> 4, qq = i & 15;
        *(uint4*)(As + r*SA_ + qq*8) =
            *(const uint4*)(A + (size_t)(rb + r)*E_ + qq*8);
    }
    #pragma unroll
    for (int i = tid; i < 8192; i += 256) {
        int k = i >> 6, n = i & 63;
        Bs[n*SA_ + k] = Wx16[(size_t)k*G_ + nb + n];
    }
    __syncthreads();

    float c[2][2][4];
    #pragma unroll
    for (int mi = 0; mi < 2; ++mi)
        #pragma unroll
        for (int ni = 0; ni < 2; ++ni)
            #pragma unroll
            for (int qq = 0; qq < 4; ++qq) c[mi][ni][qq] = 0.f;

    #pragma unroll
    for (int kk = 0; kk < 8; ++kk) {
        const int k0 = kk * 16;
        uint32_t a[2][4];
        #pragma unroll
        for (int mi = 0; mi < 2; ++mi) {
            const __half* p = As + (wm*32 + mi*16 + gid)*SA_ + k0 + 2*tig;
            a[mi][0] = *(const uint32_t*)p;
            a[mi][1] = *(const uint32_t*)(p + 8*SA_);
            a[mi][2] = *(const uint32_t*)(p + 8);
            a[mi][3] = *(const uint32_t*)(p + 8*SA_ + 8);
        }
        #pragma unroll
        for (int ni = 0; ni < 2; ++ni) {
            const __half* p = Bs + (wn*16 + ni*8 + gid)*SA_ + k0 + 2*tig;
            uint32_t b0 = *(const uint32_t*)p;
            uint32_t b1 = *(const uint32_t*)(p + 8);
            #pragma unroll
            for (int mi = 0; mi < 2; ++mi)
                mma16816(c[mi][ni], a[mi], b0, b1);
        }
    }

    #pragma unroll
    for (int ni = 0; ni < 2; ++ni) {
        int col = nb + wn*16 + ni*8 + 2*tig;
        #pragma unroll
        for (int mi = 0; mi < 2; ++mi) {
            int r0 = rb + wm*32 + mi*16 + gid;
            *(float2*)(g_xh + (size_t)r0      *G_ + col) = make_float2(c[mi][ni][0], c[mi][ni][1]);
            *(float2*)(g_xh + (size_t)(r0 + 8)*G_ + col) = make_float2(c[mi][ni][2], c[mi][ni][3]);
        }
    }
}

// ---------------- miLSTM recurrence: 2-CTA cluster per batch element ----------------
// EXACT R10-proven version (110us per launch). Comm: mbarrier count=1,
// 64 st.shared::cluster -> __syncthreads -> ONE release.cluster arrive (tid0);
// parity try_wait. 256 threads/CTA, one gate column per thread, all 128 fp32
// weights in registers. Hidden output stored as fp16 only.
__global__ void __launch_bounds__(256, 1) __cluster_dims__(2, 1, 1)
k_milstm(const float* __restrict__ Wh,
         const float* __restrict__ alpha,
         const float* __restrict__ beta1,
         const float* __restrict__ beta2,
         const float* __restrict__ bias,
         const float* __restrict__ wi,
         const float* __restrict__ wf,
         const float* __restrict__ wo,
         int layer)
{
    __shared__ float hbuf[2][128];                 // double-buffered hidden state
    __shared__ __align__(8) unsigned long long mbar;

    const int tid = threadIdx.x;
    uint32_t rank;
    asm("mov.u32 %0, %%cluster_ctarank;" : "=r"(rank));
    const int b = blockIdx.x >> 1;

    const int type = tid & 3;
    const int el   = tid >> 2;                     // 0..63
    const int gcol = type*128 + 64*(int)rank + el;

    float w[128];
    #pragma unroll
    for (int k = 0; k < 128; ++k)
        w[k] = Wh[(size_t)k*G_ + gcol];

    const float al = alpha[gcol], be1 = beta1[gcol], be2 = beta2[gcol], bi = bias[gcol];

    const int egl = 64*(int)rank + el;
    const float wie = wi[egl], wfe = wf[egl], woe = wo[egl];
    float cst = 0.f;

    if (tid < 128) { hbuf[0][tid] = 0.f; hbuf[1][tid] = 0.f; }
    if (tid == 0) {
        uint32_t ba = s2u(&mbar);
        asm volatile("mbarrier.init.shared.b64 [%0], 1;" :: "r"(ba) : "memory");
    }
    __syncthreads();
    asm volatile("barrier.cluster.arrive.aligned;" ::: "memory");
    asm volatile("barrier.cluster.wait.aligned;"   ::: "memory");

    const uint32_t bar_lo = s2u(&mbar);
    const uint32_t h_lo0  = s2u(&hbuf[0][0]);
    const uint32_t h_lo1  = s2u(&hbuf[1][0]);
    uint32_t bar_rm, h_rm0, h_rm1;
    {
        uint32_t peer = rank ^ 1u;
        asm("mapa.shared::cluster.u32 %0, %1, %2;" : "=r"(bar_rm) : "r"(bar_lo), "r"(peer));
        asm("mapa.shared::cluster.u32 %0, %1, %2;" : "=r"(h_rm0)  : "r"(h_lo0),  "r"(peer));
        asm("mapa.shared::cluster.u32 %0, %1, %2;" : "=r"(h_rm1)  : "r"(h_lo1),  "r"(peer));
    }

    const float* xhb   = g_xh + (size_t)b * T_ * G_;
    __half*      houth = layer ? g_Ah : g_h016;

    float xv = xhb[gcol];

    for (int t = 0; t < T_; ++t) {
        int tn = (t + 1 < T_) ? (t + 1) : (T_ - 1);
        float xnext = xhb[(size_t)tn * G_ + gcol];   // prefetch next step's xh

        const float* hb = hbuf[t & 1];
        float s0 = 0.f, s1 = 0.f, s2 = 0.f, s3 = 0.f;

        // ---- own-slice half of the dot BEFORE the wait (hides peer flight)
        if (rank == 0) {
            #pragma unroll
            for (int k = 0; k < 64; k += 4) {
                float4 h4 = *(const float4*)(hb + k);
                s0 = __fmaf_rn(h4.x, w[k  ], s0);
                s1 = __fmaf_rn(h4.y, w[k+1], s1);
                s2 = __fmaf_rn(h4.z, w[k+2], s2);
                s3 = __fmaf_rn(h4.w, w[k+3], s3);
            }
        } else {
            #pragma unroll
            for (int k = 64; k < 128; k += 4) {
                float4 h4 = *(const float4*)(hb + k);
                s0 = __fmaf_rn(h4.x, w[k  ], s0);
                s1 = __fmaf_rn(h4.y, w[k+1], s1);
                s2 = __fmaf_rn(h4.z, w[k+2], s2);
                s3 = __fmaf_rn(h4.w, w[k+3], s3);
            }
        }

        // ---- wait for peer's h of the previous step
        if (t > 0) {
            uint32_t par = (uint32_t)((t - 1) & 1);
            uint32_t done;
            do {
                asm volatile(
                    "{\n\t.reg .pred pp;\n\t"
                    "mbarrier.try_wait.parity.acquire.cluster.shared::cta.b64 pp, [%1], %2, 0x989680;\n\t"
                    "selp.b32 %0, 1, 0, pp;\n\t}"
                    : "=r"(done) : "r"(bar_lo), "r"(par) : "memory");
            } while (!done);
        }

        // ---- peer-slice half of the dot
        if (rank == 0) {
            #pragma unroll
            for (int k = 64; k < 128; k += 4) {
                float4 h4 = *(const float4*)(hb + k);
                s0 = __fmaf_rn(h4.x, w[k  ], s0);
                s1 = __fmaf_rn(h4.y, w[k+1], s1);
                s2 = __fmaf_rn(h4.z, w[k+2], s2);
                s3 = __fmaf_rn(h4.w, w[k+3], s3);
            }
        } else {
            #pragma unroll
            for (int k = 0; k < 64; k += 4) {
                float4 h4 = *(const float4*)(hb + k);
                s0 = __fmaf_rn(h4.x, w[k  ], s0);
                s1 = __fmaf_rn(h4.y, w[k+1], s1);
                s2 = __fmaf_rn(h4.z, w[k+2], s2);
                s3 = __fmaf_rn(h4.w, w[k+3], s3);
            }
        }
        float hh = (s0 + s1) + (s2 + s3);

        float g = xv * __fmaf_rn(al, hh, be1) + __fmaf_rn(be2, hh, bi);

        // gather i/j/f/o within the 4-lane group (independent shfls, overlap)
        float iv = __shfl_sync(0xffffffffu, g, 0, 4);
        float jv = __shfl_sync(0xffffffffu, g, 1, 4);
        float fv = __shfl_sync(0xffffffffu, g, 2, 4);
        float ov = __shfl_sync(0xffffffffu, g, 3, 4);

        iv += wie * cst;
        fv += wfe * cst;
        float cn = sigm(fv + 1.0f) * cst + sigm(iv) * ftanh(jv);
        ov += woe * cn;
        float hn = sigm(ov) * ftanh(cn);
        cst = cn;

        int nb = (t + 1) & 1;
        if (type == 0) {
            if (t < T_ - 1) {   // ship to peer asap (flight overlaps the rest)
                uint32_t ra = (nb ? h_rm1 : h_rm0) + 4u * (uint32_t)egl;
                asm volatile("st.shared::cluster.f32 [%0], %1;" :: "r"(ra), "f"(hn) : "memory");
            }
            hbuf[nb][egl] = hn;
            houth[((size_t)b * T_ + t) * E_ + egl] = __float2half(hn);
        }
        __syncthreads();   // orders: remote sts, local hbuf writes, AND all local
                           // readers of hbuf[t&1] — before the release arrive.
        if (tid == 0 && t < T_ - 1) {
            asm volatile("mbarrier.arrive.release.cluster.shared::cluster.b64 _, [%0];"
                         :: "r"(bar_rm) : "memory");
        }
        xv = xnext;
    }
}

// ---------------- projection: logits = h @ W^T + b  (fp16 HMMA) ----------------
// 2x2 grid of 128x128 sub-tiles per CTA (output 256x256), processed
// SEQUENTIALLY with the R10-proven 128x128/256-thread fragment code, so the
// 2-CTA/SM occupancy (the thing R12 lost) is preserved while A and B L2
// re-read traffic both halve: 1036 MB -> 780 MB total LTS traffic.
// smem: As0 + As1 + one Bs buffer = 3 x 34.8 KB = 102 KB; 2 CTAs/SM fit.
__global__ void __launch_bounds__(256, 2)
k_proj(const float* __restrict__ sb, float* __restrict__ out)
{
    extern __shared__ __half hsm[];
    __half* Bs = hsm + 256*SA_;     // [128][SA_] current col block

    const int tid  = threadIdx.x;
    const int wid  = tid >> 5, lane = tid & 31;
    const int gid  = lane >> 2, tig = lane & 3;
    const int wm   = wid >> 2, wn = wid & 3;      // 2 x 4 warps
    const int rb   = blockIdx.y * 256;
    const int cb   = blockIdx.x * 256;

    // load both A tiles (256 rows, contiguous in hsm)
    #pragma unroll
    for (int i = tid; i < 4096; i += 256) {
        int r = i >> 4, qq = i & 15;
        *(uint4*)(hsm + r*SA_ + qq*8) =
            *(const uint4*)(g_Ah + (size_t)(rb + r)*E_ + qq*8);
    }
    // load first B col block
    #pragma unroll
    for (int i = tid; i < 2048; i += 256) {
        int r = i >> 4, qq = i & 15;
        *(uint4*)(Bs + r*SA_ + qq*8) =
            *(const uint4*)(g_W16 + (size_t)(cb + r)*E_ + qq*8);
    }
    __syncthreads();

    #pragma unroll
    for (int nt = 0; nt < 2; ++nt) {
        const int cbase = cb + nt*128;
        if (nt == 1) {
            // reload B with the second col block (Bs reads all done at the
            // syncthreads at the end of the nt=0 iteration)
            #pragma unroll
            for (int i = tid; i < 2048; i += 256) {
                int r = i >> 4, qq = i & 15;
                *(uint4*)(Bs + r*SA_ + qq*8) =
                    *(const uint4*)(g_W16 + (size_t)(cbase + r)*E_ + qq*8);
            }
            __syncthreads();
        }

        #pragma unroll
        for (int mt = 0; mt < 2; ++mt) {
            const __half* As = hsm + mt*128*SA_;
            const int rbase = rb + mt*128;

            float c[4][4][4];
            #pragma unroll
            for (int mi = 0; mi < 4; ++mi)
                #pragma unroll
                for (int ni = 0; ni < 4; ++ni)
                    #pragma unroll
                    for (int qq = 0; qq < 4; ++qq) c[mi][ni][qq] = 0.f;

            #pragma unroll
            for (int kk = 0; kk < 8; ++kk) {
                const int k0 = kk * 16;
                uint32_t a[4][4];
                #pragma unroll
                for (int mi = 0; mi < 4; ++mi) {
                    const __half* p = As + (wm*64 + mi*16 + gid)*SA_ + k0 + 2*tig;
                    a[mi][0] = *(const uint32_t*)p;
                    a[mi][1] = *(const uint32_t*)(p + 8*SA_);
                    a[mi][2] = *(const uint32_t*)(p + 8);
                    a[mi][3] = *(const uint32_t*)(p + 8*SA_ + 8);
                }
                #pragma unroll
                for (int ni = 0; ni < 4; ++ni) {
                    const __half* p = Bs + (wn*32 + ni*8 + gid)*SA_ + k0 + 2*tig;
                    uint32_t b0 = *(const uint32_t*)p;
                    uint32_t b1 = *(const uint32_t*)(p + 8);
                    #pragma unroll
                    for (int mi = 0; mi < 4; ++mi)
                        mma16816(c[mi][ni], a[mi], b0, b1);
                }
            }

            #pragma unroll
            for (int ni = 0; ni < 4; ++ni) {
                int col = cbase + wn*32 + ni*8 + 2*tig;
                float2 bv = *(const float2*)(sb + col);
                #pragma unroll
                for (int mi = 0; mi < 4; ++mi) {
                    int r0 = rbase + wm*64 + mi*16 + gid;
                    float2 v0 = { c[mi][ni][0] + bv.x, c[mi][ni][1] + bv.y };
                    float2 v1 = { c[mi][ni][2] + bv.x, c[mi][ni][3] + bv.y };
                    *(float2*)(out + (size_t)r0      *V_ + col) = v0;
                    *(float2*)(out + (size_t)(r0 + 8)*V_ + col) = v1;
                }
            }
        }
        if (nt == 0) __syncthreads();   // all Bs reads done before reload
    }
}

// ---------------- launch ----------------
extern "C" void kernel_launch(void* const* d_in, const int* in_sizes, int n_in,
                              void* d_out, int out_size)
{
    const int*   ids   = (const int*)  d_in[0];
    const float* emb   = (const float*)d_in[1];
    const float* Wx    = (const float*)d_in[2];
    const float* Wh    = (const float*)d_in[3];
    const float* alpha = (const float*)d_in[4];
    const float* beta1 = (const float*)d_in[5];
    const float* beta2 = (const float*)d_in[6];
    const float* bias  = (const float*)d_in[7];
    const float* wi    = (const float*)d_in[8];
    const float* wf    = (const float*)d_in[9];
    const float* wo    = (const float*)d_in[10];
    const float* sw    = (const float*)d_in[11];
    const float* sbias = (const float*)d_in[12];
    float*       out   = (float*)d_out;

    const int SMEM_GEMM = (64 + 64) * SA_ * 2;            // 34816
    const int SMEM_PROJ = 3 * 128 * SA_ * 2;              // 104448

    cudaFuncSetAttribute(k_gemm_xh, cudaFuncAttributeMaxDynamicSharedMemorySize, SMEM_GEMM);
    cudaFuncSetAttribute(k_proj,    cudaFuncAttributeMaxDynamicSharedMemorySize, SMEM_PROJ);

    k_embed<<<(BT_*E_ + 255)/256, 256>>>(ids, emb);
    k_wx2half<<<(L_*E_*G_ + 255)/256, 256>>>(Wx);
    k_w2half<<<(V_*E_ + 255)/256, 256>>>(sw);

    // layer 0
    k_gemm_xh<<<dim3(G_/64, BT_/64), 256, SMEM_GEMM>>>(0, 0);
    k_milstm<<<2*B_, 256>>>(Wh, alpha, beta1, beta2, bias, wi, wf, wo, 0);

    // layer 1
    k_gemm_xh<<<dim3(G_/64, BT_/64), 256, SMEM_GEMM>>>(1, 1);
    k_milstm<<<2*B_, 256>>>(Wh + E_*G_, alpha + G_, beta1 + G_, beta2 + G_,
                            bias + G_, wi + E_, wf + E_, wo + E_, 1);

    // projection (g_Ah written directly by layer-1 milstm)
    k_proj<<<dim3(V_/256, BT_/256), 256, SMEM_PROJ>>>(sbias, out);
}

// round 14
// speedup vs baseline: 1.0929x; 1.0929x over previous
#include <cuda_runtime.h>
#include <cuda_fp16.h>
#include <cstdint>
#include <math.h>

#define V_  32000
#define E_  128
#define L_  2
#define B_  32
#define T_  128
#define G_  512          // 4*E
#define BT_ (B_*T_)      // 4096

// ---------------- device scratch (no allocations allowed) ----------------
__device__ __half g_x16 [BT_*E_];   // embedded inputs, fp16
__device__ __half g_h016[BT_*E_];   // layer-0 hidden seq, fp16 (feeds L1 gemm)
__device__ __half g_Ah  [BT_*E_];   // layer-1 hidden seq, fp16 (feeds proj)
__device__ float  g_xh [BT_*G_];    // x @ Wx for current layer (8 MB)
__device__ __half g_Wx16[L_*G_*E_]; // fp16 Wx, PRE-TRANSPOSED to [G][E] per layer
__device__ __half g_W16 [V_*E_];    // fp16 copy of softmax_w (8 MB)

__device__ __forceinline__ uint32_t s2u(const void* p)
{
    uint32_t a;
    asm("{ .reg .u64 t; cvta.to.shared.u64 t, %1; cvt.u32.u64 %0, t; }"
        : "=r"(a) : "l"(p));
    return a;
}

// ---------------- fast transcendentals (ex2/rcp approx, rel err ~1e-6) ----
__device__ __forceinline__ float sigm(float x)
{
    float e; asm("ex2.approx.ftz.f32 %0, %1;" : "=f"(e) : "f"(-1.4426950408889634f * x));
    float r; asm("rcp.approx.ftz.f32 %0, %1;" : "=f"(r) : "f"(1.0f + e));
    return r;
}
__device__ __forceinline__ float ftanh(float x)
{
    x = fmaxf(x, -40.0f);          // guard ex2 overflow -> NaN
    float e; asm("ex2.approx.ftz.f32 %0, %1;" : "=f"(e) : "f"(-2.8853900817779268f * x));
    float r; asm("rcp.approx.ftz.f32 %0, %1;" : "=f"(r) : "f"(1.0f + e));
    return (1.0f - e) * r;
}

// ---------------- embedding gather (vectorized, emit fp16) ----------------
__global__ void k_embed(const int* __restrict__ ids, const float* __restrict__ emb)
{
    int idx = blockIdx.x * blockDim.x + threadIdx.x;   // over BT_*E_/8
    if (idx < BT_*E_/8) {
        int row = idx >> 4;           // b*T + t   (16 chunks of 8 per row)
        int q   = idx & 15;
        const float* src = emb + (size_t)ids[row]*E_ + q*8;
        float4 f0 = *(const float4*)(src);
        float4 f1 = *(const float4*)(src + 4);
        __half2 h[4];
        h[0] = __floats2half2_rn(f0.x, f0.y);
        h[1] = __floats2half2_rn(f0.z, f0.w);
        h[2] = __floats2half2_rn(f1.x, f1.y);
        h[3] = __floats2half2_rn(f1.z, f1.w);
        *(uint4*)(g_x16 + (size_t)row*E_ + q*8) = *(uint4*)h;
    }
}

// ---------------- fp32 -> fp16 weight converts ----------------
__global__ void k_w2half(const float* __restrict__ w)
{
    int idx = blockIdx.x * blockDim.x + threadIdx.x;
    if (idx < V_*E_) g_W16[idx] = __float2half(w[idx]);
}
// Wx [L][E][G] (k-major) -> g_Wx16 [L][G][E] (n-major, pre-transposed so the
// GEMM's B-tile load is a vectorized row copy instead of 8192 scalar stores)
__global__ void k_wx2half(const float* __restrict__ wx)
{
    int idx = blockIdx.x * blockDim.x + threadIdx.x;
    if (idx < L_*G_*E_) {
        int l = idx / (G_*E_);
        int r = idx % (G_*E_);
        int g = r / E_;
        int e = r % E_;
        g_Wx16[idx] = __float2half(wx[(size_t)l*E_*G_ + (size_t)e*G_ + g]);
    }
}

// ---------------- HMMA helper ----------------
__device__ __forceinline__ void mma16816(float* c, const uint32_t* a,
                                         uint32_t b0, uint32_t b1)
{
    asm volatile(
        "mma.sync.aligned.m16n8k16.row.col.f32.f16.f16.f32 "
        "{%0,%1,%2,%3}, {%4,%5,%6,%7}, {%8,%9}, {%0,%1,%2,%3};\n"
        : "+f"(c[0]), "+f"(c[1]), "+f"(c[2]), "+f"(c[3])
        : "r"(a[0]), "r"(a[1]), "r"(a[2]), "r"(a[3]), "r"(b0), "r"(b1));
}

#define SA_ 136   // padded smem row in halves

// ---------------- xh GEMM (fp16 HMMA): (BT x E) @ (E x G) -> g_xh ----------------
// A = g_x16 (src=0) or g_h016 (src=1), row-major [BT][E].
// B tile rows come straight from the pre-transposed g_Wx16 [G][E] via uint4.
__global__ void __launch_bounds__(256, 2)
k_gemm_xh(int layer, int src)
{
    const __half* A   = src ? g_h016 : g_x16;
    const __half* Wxt = g_Wx16 + (size_t)layer * G_ * E_;
    extern __shared__ __half gsm[];
    __half* As = gsm;              // [64][SA_]
    __half* Bs = gsm + 64*SA_;     // [64][SA_]  (n-major, k contiguous)

    const int tid  = threadIdx.x;
    const int wid  = tid >> 5, lane = tid & 31;
    const int gid  = lane >> 2, tig = lane & 3;
    const int wm   = wid >> 2, wn = wid & 3;      // 2 x 4 warps
    const int rb   = blockIdx.y * 64;
    const int nb   = blockIdx.x * 64;

    #pragma unroll
    for (int i = tid; i < 1024; i += 256) {
        int r = i >> 4, qq = i & 15;
        *(uint4*)(As + r*SA_ + qq*8) =
            *(const uint4*)(A + (size_t)(rb + r)*E_ + qq*8);
    }
    #pragma unroll
    for (int i = tid; i < 1024; i += 256) {
        int r = i >> 4, qq = i & 15;
        *(uint4*)(Bs + r*SA_ + qq*8) =
            *(const uint4*)(Wxt + (size_t)(nb + r)*E_ + qq*8);
    }
    __syncthreads();

    float c[2][2][4];
    #pragma unroll
    for (int mi = 0; mi < 2; ++mi)
        #pragma unroll
        for (int ni = 0; ni < 2; ++ni)
            #pragma unroll
            for (int qq = 0; qq < 4; ++qq) c[mi][ni][qq] = 0.f;

    #pragma unroll
    for (int kk = 0; kk < 8; ++kk) {
        const int k0 = kk * 16;
        uint32_t a[2][4];
        #pragma unroll
        for (int mi = 0; mi < 2; ++mi) {
            const __half* p = As + (wm*32 + mi*16 + gid)*SA_ + k0 + 2*tig;
            a[mi][0] = *(const uint32_t*)p;
            a[mi][1] = *(const uint32_t*)(p + 8*SA_);
            a[mi][2] = *(const uint32_t*)(p + 8);
            a[mi][3] = *(const uint32_t*)(p + 8*SA_ + 8);
        }
        #pragma unroll
        for (int ni = 0; ni < 2; ++ni) {
            const __half* p = Bs + (wn*16 + ni*8 + gid)*SA_ + k0 + 2*tig;
            uint32_t b0 = *(const uint32_t*)p;
            uint32_t b1 = *(const uint32_t*)(p + 8);
            #pragma unroll
            for (int mi = 0; mi < 2; ++mi)
                mma16816(c[mi][ni], a[mi], b0, b1);
        }
    }

    #pragma unroll
    for (int ni = 0; ni < 2; ++ni) {
        int col = nb + wn*16 + ni*8 + 2*tig;
        #pragma unroll
        for (int mi = 0; mi < 2; ++mi) {
            int r0 = rb + wm*32 + mi*16 + gid;
            *(float2*)(g_xh + (size_t)r0      *G_ + col) = make_float2(c[mi][ni][0], c[mi][ni][1]);
            *(float2*)(g_xh + (size_t)(r0 + 8)*G_ + col) = make_float2(c[mi][ni][2], c[mi][ni][3]);
        }
    }
}

// ---------------- miLSTM recurrence: 2-CTA cluster per batch element ----------------
// EXACT R10-proven version (110us per launch). Comm: mbarrier count=1,
// 64 st.shared::cluster -> __syncthreads -> ONE release.cluster arrive (tid0);
// parity try_wait. 256 threads/CTA, one gate column per thread, all 128 fp32
// weights in registers. Hidden output stored as fp16 only.
__global__ void __launch_bounds__(256, 1) __cluster_dims__(2, 1, 1)
k_milstm(const float* __restrict__ Wh,
         const float* __restrict__ alpha,
         const float* __restrict__ beta1,
         const float* __restrict__ beta2,
         const float* __restrict__ bias,
         const float* __restrict__ wi,
         const float* __restrict__ wf,
         const float* __restrict__ wo,
         int layer)
{
    __shared__ float hbuf[2][128];                 // double-buffered hidden state
    __shared__ __align__(8) unsigned long long mbar;

    const int tid = threadIdx.x;
    uint32_t rank;
    asm("mov.u32 %0, %%cluster_ctarank;" : "=r"(rank));
    const int b = blockIdx.x >> 1;

    const int type = tid & 3;
    const int el   = tid >> 2;                     // 0..63
    const int gcol = type*128 + 64*(int)rank + el;

    float w[128];
    #pragma unroll
    for (int k = 0; k < 128; ++k)
        w[k] = Wh[(size_t)k*G_ + gcol];

    const float al = alpha[gcol], be1 = beta1[gcol], be2 = beta2[gcol], bi = bias[gcol];

    const int egl = 64*(int)rank + el;
    const float wie = wi[egl], wfe = wf[egl], woe = wo[egl];
    float cst = 0.f;

    if (tid < 128) { hbuf[0][tid] = 0.f; hbuf[1][tid] = 0.f; }
    if (tid == 0) {
        uint32_t ba = s2u(&mbar);
        asm volatile("mbarrier.init.shared.b64 [%0], 1;" :: "r"(ba) : "memory");
    }
    __syncthreads();
    asm volatile("barrier.cluster.arrive.aligned;" ::: "memory");
    asm volatile("barrier.cluster.wait.aligned;"   ::: "memory");

    const uint32_t bar_lo = s2u(&mbar);
    const uint32_t h_lo0  = s2u(&hbuf[0][0]);
    const uint32_t h_lo1  = s2u(&hbuf[1][0]);
    uint32_t bar_rm, h_rm0, h_rm1;
    {
        uint32_t peer = rank ^ 1u;
        asm("mapa.shared::cluster.u32 %0, %1, %2;" : "=r"(bar_rm) : "r"(bar_lo), "r"(peer));
        asm("mapa.shared::cluster.u32 %0, %1, %2;" : "=r"(h_rm0)  : "r"(h_lo0),  "r"(peer));
        asm("mapa.shared::cluster.u32 %0, %1, %2;" : "=r"(h_rm1)  : "r"(h_lo1),  "r"(peer));
    }

    const float* xhb   = g_xh + (size_t)b * T_ * G_;
    __half*      houth = layer ? g_Ah : g_h016;

    float xv = xhb[gcol];

    for (int t = 0; t < T_; ++t) {
        int tn = (t + 1 < T_) ? (t + 1) : (T_ - 1);
        float xnext = xhb[(size_t)tn * G_ + gcol];   // prefetch next step's xh

        const float* hb = hbuf[t & 1];
        float s0 = 0.f, s1 = 0.f, s2 = 0.f, s3 = 0.f;

        // ---- own-slice half of the dot BEFORE the wait (hides peer flight)
        if (rank == 0) {
            #pragma unroll
            for (int k = 0; k < 64; k += 4) {
                float4 h4 = *(const float4*)(hb + k);
                s0 = __fmaf_rn(h4.x, w[k  ], s0);
                s1 = __fmaf_rn(h4.y, w[k+1], s1);
                s2 = __fmaf_rn(h4.z, w[k+2], s2);
                s3 = __fmaf_rn(h4.w, w[k+3], s3);
            }
        } else {
            #pragma unroll
            for (int k = 64; k < 128; k += 4) {
                float4 h4 = *(const float4*)(hb + k);
                s0 = __fmaf_rn(h4.x, w[k  ], s0);
                s1 = __fmaf_rn(h4.y, w[k+1], s1);
                s2 = __fmaf_rn(h4.z, w[k+2], s2);
                s3 = __fmaf_rn(h4.w, w[k+3], s3);
            }
        }

        // ---- wait for peer's h of the previous step
        if (t > 0) {
            uint32_t par = (uint32_t)((t - 1) & 1);
            uint32_t done;
            do {
                asm volatile(
                    "{\n\t.reg .pred pp;\n\t"
                    "mbarrier.try_wait.parity.acquire.cluster.shared::cta.b64 pp, [%1], %2, 0x989680;\n\t"
                    "selp.b32 %0, 1, 0, pp;\n\t}"
                    : "=r"(done) : "r"(bar_lo), "r"(par) : "memory");
            } while (!done);
        }

        // ---- peer-slice half of the dot
        if (rank == 0) {
            #pragma unroll
            for (int k = 64; k < 128; k += 4) {
                float4 h4 = *(const float4*)(hb + k);
                s0 = __fmaf_rn(h4.x, w[k  ], s0);
                s1 = __fmaf_rn(h4.y, w[k+1], s1);
                s2 = __fmaf_rn(h4.z, w[k+2], s2);
                s3 = __fmaf_rn(h4.w, w[k+3], s3);
            }
        } else {
            #pragma unroll
            for (int k = 0; k < 64; k += 4) {
                float4 h4 = *(const float4*)(hb + k);
                s0 = __fmaf_rn(h4.x, w[k  ], s0);
                s1 = __fmaf_rn(h4.y, w[k+1], s1);
                s2 = __fmaf_rn(h4.z, w[k+2], s2);
                s3 = __fmaf_rn(h4.w, w[k+3], s3);
            }
        }
        float hh = (s0 + s1) + (s2 + s3);

        float g = xv * __fmaf_rn(al, hh, be1) + __fmaf_rn(be2, hh, bi);

        // gather i/j/f/o within the 4-lane group (independent shfls, overlap)
        float iv = __shfl_sync(0xffffffffu, g, 0, 4);
        float jv = __shfl_sync(0xffffffffu, g, 1, 4);
        float fv = __shfl_sync(0xffffffffu, g, 2, 4);
        float ov = __shfl_sync(0xffffffffu, g, 3, 4);

        iv += wie * cst;
        fv += wfe * cst;
        float cn = sigm(fv + 1.0f) * cst + sigm(iv) * ftanh(jv);
        ov += woe * cn;
        float hn = sigm(ov) * ftanh(cn);
        cst = cn;

        int nb = (t + 1) & 1;
        if (type == 0) {
            if (t < T_ - 1) {   // ship to peer asap (flight overlaps the rest)
                uint32_t ra = (nb ? h_rm1 : h_rm0) + 4u * (uint32_t)egl;
                asm volatile("st.shared::cluster.f32 [%0], %1;" :: "r"(ra), "f"(hn) : "memory");
            }
            hbuf[nb][egl] = hn;
            houth[((size_t)b * T_ + t) * E_ + egl] = __float2half(hn);
        }
        __syncthreads();   // orders: remote sts, local hbuf writes, AND all local
                           // readers of hbuf[t&1] — before the release arrive.
        if (tid == 0 && t < T_ - 1) {
            asm volatile("mbarrier.arrive.release.cluster.shared::cluster.b64 _, [%0];"
                         :: "r"(bar_rm) : "memory");
        }
        xv = xnext;
    }
}

// ---------------- projection: logits = h @ W^T + b  (fp16 HMMA) ----------------
// EXACT R10-proven version: 128x128 tile, 256 threads, 2 CTAs/SM.
__global__ void __launch_bounds__(256, 2)
k_proj(const float* __restrict__ sb, float* __restrict__ out)
{
    extern __shared__ __half hsm[];
    __half* As = hsm;               // [128][SA_]
    __half* Bs = hsm + 128*SA_;     // [128][SA_]

    const int tid  = threadIdx.x;
    const int wid  = tid >> 5, lane = tid & 31;
    const int gid  = lane >> 2, tig = lane & 3;
    const int wm   = wid >> 2, wn = wid & 3;
    const int rb   = blockIdx.y * 128;
    const int cb   = blockIdx.x * 128;

    #pragma unroll
    for (int i = tid; i < 2048; i += 256) {
        int r = i >> 4, qq = i & 15;
        *(uint4*)(As + r*SA_ + qq*8) =
            *(const uint4*)(g_Ah + (size_t)(rb + r)*E_ + qq*8);
    }
    #pragma unroll
    for (int i = tid; i < 2048; i += 256) {
        int r = i >> 4, qq = i & 15;
        *(uint4*)(Bs + r*SA_ + qq*8) =
            *(const uint4*)(g_W16 + (size_t)(cb + r)*E_ + qq*8);
    }
    __syncthreads();

    float c[4][4][4];
    #pragma unroll
    for (int mi = 0; mi < 4; ++mi)
        #pragma unroll
        for (int ni = 0; ni < 4; ++ni)
            #pragma unroll
            for (int qq = 0; qq < 4; ++qq) c[mi][ni][qq] = 0.f;

    #pragma unroll
    for (int kk = 0; kk < 8; ++kk) {
        const int k0 = kk * 16;
        uint32_t a[4][4];
        #pragma unroll
        for (int mi = 0; mi < 4; ++mi) {
            const __half* p = As + (wm*64 + mi*16 + gid)*SA_ + k0 + 2*tig;
            a[mi][0] = *(const uint32_t*)p;
            a[mi][1] = *(const uint32_t*)(p + 8*SA_);
            a[mi][2] = *(const uint32_t*)(p + 8);
            a[mi][3] = *(const uint32_t*)(p + 8*SA_ + 8);
        }
        #pragma unroll
        for (int ni = 0; ni < 4; ++ni) {
            const __half* p = Bs + (wn*32 + ni*8 + gid)*SA_ + k0 + 2*tig;
            uint32_t b0 = *(const uint32_t*)p;
            uint32_t b1 = *(const uint32_t*)(p + 8);
            #pragma unroll
            for (int mi = 0; mi < 4; ++mi)
                mma16816(c[mi][ni], a[mi], b0, b1);
        }
    }

    #pragma unroll
    for (int ni = 0; ni < 4; ++ni) {
        int col = cb + wn*32 + ni*8 + 2*tig;
        float2 bv = *(const float2*)(sb + col);
        #pragma unroll
        for (int mi = 0; mi < 4; ++mi) {
            int r0 = rb + wm*64 + mi*16 + gid;
            float2 v0 = { c[mi][ni][0] + bv.x, c[mi][ni][1] + bv.y };
            float2 v1 = { c[mi][ni][2] + bv.x, c[mi][ni][3] + bv.y };
            *(float2*)(out + (size_t)r0      *V_ + col) = v0;
            *(float2*)(out + (size_t)(r0 + 8)*V_ + col) = v1;
        }
    }
}

// ---------------- launch ----------------
extern "C" void kernel_launch(void* const* d_in, const int* in_sizes, int n_in,
                              void* d_out, int out_size)
{
    const int*   ids   = (const int*)  d_in[0];
    const float* emb   = (const float*)d_in[1];
    const float* Wx    = (const float*)d_in[2];
    const float* Wh    = (const float*)d_in[3];
    const float* alpha = (const float*)d_in[4];
    const float* beta1 = (const float*)d_in[5];
    const float* beta2 = (const float*)d_in[6];
    const float* bias  = (const float*)d_in[7];
    const float* wi    = (const float*)d_in[8];
    const float* wf    = (const float*)d_in[9];
    const float* wo    = (const float*)d_in[10];
    const float* sw    = (const float*)d_in[11];
    const float* sbias = (const float*)d_in[12];
    float*       out   = (float*)d_out;

    const int SMEM_GEMM = (64 + 64) * SA_ * 2;            // 34816
    const int SMEM_PROJ = 2 * 128 * SA_ * 2;              // 69632

    cudaFuncSetAttribute(k_gemm_xh, cudaFuncAttributeMaxDynamicSharedMemorySize, SMEM_GEMM);
    cudaFuncSetAttribute(k_proj,    cudaFuncAttributeMaxDynamicSharedMemorySize, SMEM_PROJ);

    k_embed<<<(BT_*E_/8 + 255)/256, 256>>>(ids, emb);
    k_wx2half<<<(L_*G_*E_ + 255)/256, 256>>>(Wx);
    k_w2half<<<(V_*E_ + 255)/256, 256>>>(sw);

    // layer 0
    k_gemm_xh<<<dim3(G_/64, BT_/64), 256, SMEM_GEMM>>>(0, 0);
    k_milstm<<<2*B_, 256>>>(Wh, alpha, beta1, beta2, bias, wi, wf, wo, 0);

    // layer 1
    k_gemm_xh<<<dim3(G_/64, BT_/64), 256, SMEM_GEMM>>>(1, 1);
    k_milstm<<<2*B_, 256>>>(Wh + E_*G_, alpha + G_, beta1 + G_, beta2 + G_,
                            bias + G_, wi + E_, wf + E_, wo + E_, 1);

    // projection (g_Ah written directly by layer-1 milstm)
    k_proj<<<dim3(V_/128, BT_/128), 256, SMEM_PROJ>>>(sbias, out);
}

// round 15
// speedup vs baseline: 1.2553x; 1.1485x over previous
#include <cuda_runtime.h>
#include <cuda_fp16.h>
#include <cstdint>
#include <math.h>

#define V_  32000
#define E_  128
#define L_  2
#define B_  32
#define T_  128
#define G_  512          // 4*E
#define BT_ (B_*T_)      // 4096

// ---------------- device scratch (no allocations allowed) ----------------
__device__ __half g_x16 [BT_*E_];   // embedded inputs, fp16
__device__ __half g_h016[BT_*E_];   // layer-0 hidden seq, fp16 (feeds L1 gemm)
__device__ __half g_Ah  [BT_*E_];   // layer-1 hidden seq, fp16 (feeds proj)
__device__ float  g_xh [BT_*G_];    // x @ Wx for current layer (8 MB)
__device__ __half g_Wx16[L_*G_*E_]; // fp16 Wx, PRE-TRANSPOSED to [G][E] per layer
__device__ __half g_W16 [V_*E_];    // fp16 copy of softmax_w (8 MB)

__device__ __forceinline__ uint32_t s2u(const void* p)
{
    uint32_t a;
    asm("{ .reg .u64 t; cvta.to.shared.u64 t, %1; cvt.u32.u64 %0, t; }"
        : "=r"(a) : "l"(p));
    return a;
}

// ---------------- fast transcendentals (ex2/rcp approx, rel err ~1e-6) ----
__device__ __forceinline__ float sigm(float x)
{
    float e; asm("ex2.approx.ftz.f32 %0, %1;" : "=f"(e) : "f"(-1.4426950408889634f * x));
    float r; asm("rcp.approx.ftz.f32 %0, %1;" : "=f"(r) : "f"(1.0f + e));
    return r;
}
__device__ __forceinline__ float ftanh(float x)
{
    x = fmaxf(x, -40.0f);          // guard ex2 overflow -> NaN
    float e; asm("ex2.approx.ftz.f32 %0, %1;" : "=f"(e) : "f"(-2.8853900817779268f * x));
    float r; asm("rcp.approx.ftz.f32 %0, %1;" : "=f"(r) : "f"(1.0f + e));
    return (1.0f - e) * r;
}

// ---------------- embedding gather (vectorized, emit fp16) ----------------
__global__ void k_embed(const int* __restrict__ ids, const float* __restrict__ emb)
{
    int idx = blockIdx.x * blockDim.x + threadIdx.x;   // over BT_*E_/8
    if (idx < BT_*E_/8) {
        int row = idx >> 4;           // b*T + t   (16 chunks of 8 per row)
        int q   = idx & 15;
        const float* src = emb + (size_t)ids[row]*E_ + q*8;
        float4 f0 = *(const float4*)(src);
        float4 f1 = *(const float4*)(src + 4);
        __half2 h[4];
        h[0] = __floats2half2_rn(f0.x, f0.y);
        h[1] = __floats2half2_rn(f0.z, f0.w);
        h[2] = __floats2half2_rn(f1.x, f1.y);
        h[3] = __floats2half2_rn(f1.z, f1.w);
        *(uint4*)(g_x16 + (size_t)row*E_ + q*8) = *(uint4*)h;
    }
}

// ---------------- fp32 -> fp16 weight converts ----------------
__global__ void k_w2half(const float* __restrict__ w)
{
    int idx = blockIdx.x * blockDim.x + threadIdx.x;
    if (idx < V_*E_) g_W16[idx] = __float2half(w[idx]);
}
// Wx [L][E][G] (k-major) -> g_Wx16 [L][G][E] (n-major, pre-transposed)
__global__ void k_wx2half(const float* __restrict__ wx)
{
    int idx = blockIdx.x * blockDim.x + threadIdx.x;
    if (idx < L_*G_*E_) {
        int l = idx / (G_*E_);
        int r = idx % (G_*E_);
        int g = r / E_;
        int e = r % E_;
        g_Wx16[idx] = __float2half(wx[(size_t)l*E_*G_ + (size_t)e*G_ + g]);
    }
}

// ---------------- HMMA helper ----------------
__device__ __forceinline__ void mma16816(float* c, const uint32_t* a,
                                         uint32_t b0, uint32_t b1)
{
    asm volatile(
        "mma.sync.aligned.m16n8k16.row.col.f32.f16.f16.f32 "
        "{%0,%1,%2,%3}, {%4,%5,%6,%7}, {%8,%9}, {%0,%1,%2,%3};\n"
        : "+f"(c[0]), "+f"(c[1]), "+f"(c[2]), "+f"(c[3])
        : "r"(a[0]), "r"(a[1]), "r"(a[2]), "r"(a[3]), "r"(b0), "r"(b1));
}

#define SA_ 136   // padded smem row in halves

// ---------------- xh GEMM (fp16 HMMA): (BT x E) @ (E x G) -> g_xh ----------------
__global__ void __launch_bounds__(256, 2)
k_gemm_xh(int layer, int src)
{
    const __half* A   = src ? g_h016 : g_x16;
    const __half* Wxt = g_Wx16 + (size_t)layer * G_ * E_;
    extern __shared__ __half gsm[];
    __half* As = gsm;              // [64][SA_]
    __half* Bs = gsm + 64*SA_;     // [64][SA_]  (n-major, k contiguous)

    const int tid  = threadIdx.x;
    const int wid  = tid >> 5, lane = tid & 31;
    const int gid  = lane >> 2, tig = lane & 3;
    const int wm   = wid >> 2, wn = wid & 3;      // 2 x 4 warps
    const int rb   = blockIdx.y * 64;
    const int nb   = blockIdx.x * 64;

    #pragma unroll
    for (int i = tid; i < 1024; i += 256) {
        int r = i >> 4, qq = i & 15;
        *(uint4*)(As + r*SA_ + qq*8) =
            *(const uint4*)(A + (size_t)(rb + r)*E_ + qq*8);
    }
    #pragma unroll
    for (int i = tid; i < 1024; i += 256) {
        int r = i >> 4, qq = i & 15;
        *(uint4*)(Bs + r*SA_ + qq*8) =
            *(const uint4*)(Wxt + (size_t)(nb + r)*E_ + qq*8);
    }
    __syncthreads();

    float c[2][2][4];
    #pragma unroll
    for (int mi = 0; mi < 2; ++mi)
        #pragma unroll
        for (int ni = 0; ni < 2; ++ni)
            #pragma unroll
            for (int qq = 0; qq < 4; ++qq) c[mi][ni][qq] = 0.f;

    #pragma unroll
    for (int kk = 0; kk < 8; ++kk) {
        const int k0 = kk * 16;
        uint32_t a[2][4];
        #pragma unroll
        for (int mi = 0; mi < 2; ++mi) {
            const __half* p = As + (wm*32 + mi*16 + gid)*SA_ + k0 + 2*tig;
            a[mi][0] = *(const uint32_t*)p;
            a[mi][1] = *(const uint32_t*)(p + 8*SA_);
            a[mi][2] = *(const uint32_t*)(p + 8);
            a[mi][3] = *(const uint32_t*)(p + 8*SA_ + 8);
        }
        #pragma unroll
        for (int ni = 0; ni < 2; ++ni) {
            const __half* p = Bs + (wn*16 + ni*8 + gid)*SA_ + k0 + 2*tig;
            uint32_t b0 = *(const uint32_t*)p;
            uint32_t b1 = *(const uint32_t*)(p + 8);
            #pragma unroll
            for (int mi = 0; mi < 2; ++mi)
                mma16816(c[mi][ni], a[mi], b0, b1);
        }
    }

    #pragma unroll
    for (int ni = 0; ni < 2; ++ni) {
        int col = nb + wn*16 + ni*8 + 2*tig;
        #pragma unroll
        for (int mi = 0; mi < 2; ++mi) {
            int r0 = rb + wm*32 + mi*16 + gid;
            *(float2*)(g_xh + (size_t)r0      *G_ + col) = make_float2(c[mi][ni][0], c[mi][ni][1]);
            *(float2*)(g_xh + (size_t)(r0 + 8)*G_ + col) = make_float2(c[mi][ni][2], c[mi][ni][3]);
        }
    }
}

// ---------------- miLSTM recurrence: 2-CTA cluster per batch element ----------------
// R15 comm: st.async + double-buffered TRANSACTION mbarriers. Data and
// completion travel in ONE DSMEM flight — removes the release-arrive's
// store-drain (~215cyc) AND its separate flight (~215cyc) from the R14 path.
// Protocol (per barrier b in {0,1}, local to the RECEIVER, init count=1):
//   - setup: tid0 inits both, then arrive.expect_tx(256B) on both (arms ph 0).
//   - sender step t (t<T-1): 64 lanes st.async h(t) -> peer hbuf[(t+1)&1],
//     completing tx on peer's bar[(t+1)&1].
//   - receiver step t (t>0): parity-wait bar[t&1] (phase (t-1-((t-1)&1))/2 ...
//     tracked by a toggling par[] counter), then tid0 re-arms that barrier
//     (arrive.expect_tx) for its use at t+2. Causality: my re-arm precedes my
//     step-t sends, which precede (via peer's wait) the peer's step-(t+1)
//     sends back into this barrier — so tx can never outrun the re-arm's
//     arrive by a full phase. Transiently-early tx (negative count) is
//     architecturally supported.
//   - exit: last send at t=T-2 is consumed by peer's wait at T-1 before exit.
// Waits are BOUNDED (cap ~64K tries, 512ns hint): a protocol bug degrades to
// a wrong answer (diagnosable) instead of a 120s timeout.
__global__ void __launch_bounds__(256, 1) __cluster_dims__(2, 1, 1)
k_milstm(const float* __restrict__ Wh,
         const float* __restrict__ alpha,
         const float* __restrict__ beta1,
         const float* __restrict__ beta2,
         const float* __restrict__ bias,
         const float* __restrict__ wi,
         const float* __restrict__ wf,
         const float* __restrict__ wo,
         int layer)
{
    __shared__ float hbuf[2][128];                 // double-buffered hidden state
    __shared__ __align__(16) unsigned long long mbar[2];

    const int tid = threadIdx.x;
    uint32_t rank;
    asm("mov.u32 %0, %%cluster_ctarank;" : "=r"(rank));
    const int b = blockIdx.x >> 1;

    const int type = tid & 3;
    const int el   = tid >> 2;                     // 0..63
    const int gcol = type*128 + 64*(int)rank + el;

    float w[128];
    #pragma unroll
    for (int k = 0; k < 128; ++k)
        w[k] = Wh[(size_t)k*G_ + gcol];

    const float al = alpha[gcol], be1 = beta1[gcol], be2 = beta2[gcol], bi = bias[gcol];

    const int egl = 64*(int)rank + el;
    const float wie = wi[egl], wfe = wf[egl], woe = wo[egl];
    float cst = 0.f;

    const uint32_t b0_lo = s2u(&mbar[0]);
    const uint32_t b1_lo = s2u(&mbar[1]);
    if (tid < 128) { hbuf[0][tid] = 0.f; hbuf[1][tid] = 0.f; }
    if (tid == 0) {
        asm volatile("mbarrier.init.shared.b64 [%0], 1;" :: "r"(b0_lo) : "memory");
        asm volatile("mbarrier.init.shared.b64 [%0], 1;" :: "r"(b1_lo) : "memory");
        asm volatile("mbarrier.arrive.expect_tx.shared.b64 _, [%0], %1;" :: "r"(b0_lo), "r"(256) : "memory");
        asm volatile("mbarrier.arrive.expect_tx.shared.b64 _, [%0], %1;" :: "r"(b1_lo), "r"(256) : "memory");
    }
    __syncthreads();
    asm volatile("barrier.cluster.arrive.aligned;" ::: "memory");
    asm volatile("barrier.cluster.wait.aligned;"   ::: "memory");

    const uint32_t h_lo0 = s2u(&hbuf[0][0]);
    const uint32_t h_lo1 = s2u(&hbuf[1][0]);
    uint32_t b0_rm, b1_rm, h_rm0, h_rm1;
    {
        uint32_t peer = rank ^ 1u;
        asm("mapa.shared::cluster.u32 %0, %1, %2;" : "=r"(b0_rm) : "r"(b0_lo), "r"(peer));
        asm("mapa.shared::cluster.u32 %0, %1, %2;" : "=r"(b1_rm) : "r"(b1_lo), "r"(peer));
        asm("mapa.shared::cluster.u32 %0, %1, %2;" : "=r"(h_rm0) : "r"(h_lo0), "r"(peer));
        asm("mapa.shared::cluster.u32 %0, %1, %2;" : "=r"(h_rm1) : "r"(h_lo1), "r"(peer));
    }

    const float* xhb   = g_xh + (size_t)b * T_ * G_;
    __half*      houth = layer ? g_Ah : g_h016;

    float xv = xhb[gcol];
    uint32_t par0 = 0u, par1 = 0u;   // wait-parity per barrier

    for (int t = 0; t < T_; ++t) {
        int tn = (t + 1 < T_) ? (t + 1) : (T_ - 1);
        float xnext = xhb[(size_t)tn * G_ + gcol];   // prefetch next step's xh

        const float* hb = hbuf[t & 1];
        float s0 = 0.f, s1 = 0.f, s2 = 0.f, s3 = 0.f;

        // ---- own-slice half of the dot BEFORE the wait (hides peer flight)
        if (rank == 0) {
            #pragma unroll
            for (int k = 0; k < 64; k += 4) {
                float4 h4 = *(const float4*)(hb + k);
                s0 = __fmaf_rn(h4.x, w[k  ], s0);
                s1 = __fmaf_rn(h4.y, w[k+1], s1);
                s2 = __fmaf_rn(h4.z, w[k+2], s2);
                s3 = __fmaf_rn(h4.w, w[k+3], s3);
            }
        } else {
            #pragma unroll
            for (int k = 64; k < 128; k += 4) {
                float4 h4 = *(const float4*)(hb + k);
                s0 = __fmaf_rn(h4.x, w[k  ], s0);
                s1 = __fmaf_rn(h4.y, w[k+1], s1);
                s2 = __fmaf_rn(h4.z, w[k+2], s2);
                s3 = __fmaf_rn(h4.w, w[k+3], s3);
            }
        }

        // ---- wait for peer's h of the previous step (tx barrier, bounded)
        if (t > 0) {
            uint32_t blo = (t & 1) ? b1_lo : b0_lo;
            uint32_t p   = (t & 1) ? par1  : par0;
            uint32_t done;
            int spins = 0;
            do {
                asm volatile(
                    "{\n\t.reg .pred pp;\n\t"
                    "mbarrier.try_wait.parity.acquire.cluster.shared::cta.b64 pp, [%1], %2, 0x200;\n\t"
                    "selp.b32 %0, 1, 0, pp;\n\t}"
                    : "=r"(done) : "r"(blo), "r"(p) : "memory");
            } while (!done && ++spins < 65536);
            if (t & 1) par1 ^= 1u; else par0 ^= 1u;
            // re-arm this barrier for its use at step t+2 (before our sends)
            if (tid == 0)
                asm volatile("mbarrier.arrive.expect_tx.shared.b64 _, [%0], %1;"
                             :: "r"(blo), "r"(256) : "memory");
        }

        // ---- peer-slice half of the dot
        if (rank == 0) {
            #pragma unroll
            for (int k = 64; k < 128; k += 4) {
                float4 h4 = *(const float4*)(hb + k);
                s0 = __fmaf_rn(h4.x, w[k  ], s0);
                s1 = __fmaf_rn(h4.y, w[k+1], s1);
                s2 = __fmaf_rn(h4.z, w[k+2], s2);
                s3 = __fmaf_rn(h4.w, w[k+3], s3);
            }
        } else {
            #pragma unroll
            for (int k = 0; k < 64; k += 4) {
                float4 h4 = *(const float4*)(hb + k);
                s0 = __fmaf_rn(h4.x, w[k  ], s0);
                s1 = __fmaf_rn(h4.y, w[k+1], s1);
                s2 = __fmaf_rn(h4.z, w[k+2], s2);
                s3 = __fmaf_rn(h4.w, w[k+3], s3);
            }
        }
        float hh = (s0 + s1) + (s2 + s3);

        float g = xv * __fmaf_rn(al, hh, be1) + __fmaf_rn(be2, hh, bi);

        // gather i/j/f/o within the 4-lane group (independent shfls, overlap)
        float iv = __shfl_sync(0xffffffffu, g, 0, 4);
        float jv = __shfl_sync(0xffffffffu, g, 1, 4);
        float fv = __shfl_sync(0xffffffffu, g, 2, 4);
        float ov = __shfl_sync(0xffffffffu, g, 3, 4);

        iv += wie * cst;
        fv += wfe * cst;
        float cn = sigm(fv + 1.0f) * cst + sigm(iv) * ftanh(jv);
        ov += woe * cn;
        float hn = sigm(ov) * ftanh(cn);
        cst = cn;

        int nb = (t + 1) & 1;
        if (type == 0) {
            if (t < T_ - 1) {
                // data + tx-completion to peer in ONE flight
                uint32_t ra = (nb ? h_rm1 : h_rm0) + 4u * (uint32_t)egl;
                uint32_t rb = nb ? b1_rm : b0_rm;
                asm volatile(
                    "st.async.shared::cluster.mbarrier::complete_tx::bytes.b32 [%0], %1, [%2];"
                    :: "r"(ra), "r"(__float_as_uint(hn)), "r"(rb) : "memory");
            }
            hbuf[nb][egl] = hn;
            houth[((size_t)b * T_ + t) * E_ + egl] = __float2half(hn);
        }
        __syncthreads();   // local hbuf[nb] visible before next step's dot
        xv = xnext;
    }
}

// ---------------- projection: logits = h @ W^T + b  (fp16 HMMA) ----------------
// EXACT R10-proven version: 128x128 tile, 256 threads, 2 CTAs/SM.
__global__ void __launch_bounds__(256, 2)
k_proj(const float* __restrict__ sb, float* __restrict__ out)
{
    extern __shared__ __half hsm[];
    __half* As = hsm;               // [128][SA_]
    __half* Bs = hsm + 128*SA_;     // [128][SA_]

    const int tid  = threadIdx.x;
    const int wid  = tid >> 5, lane = tid & 31;
    const int gid  = lane >> 2, tig = lane & 3;
    const int wm   = wid >> 2, wn = wid & 3;
    const int rb   = blockIdx.y * 128;
    const int cb   = blockIdx.x * 128;

    #pragma unroll
    for (int i = tid; i < 2048; i += 256) {
        int r = i >> 4, qq = i & 15;
        *(uint4*)(As + r*SA_ + qq*8) =
            *(const uint4*)(g_Ah + (size_t)(rb + r)*E_ + qq*8);
    }
    #pragma unroll
    for (int i = tid; i < 2048; i += 256) {
        int r = i >> 4, qq = i & 15;
        *(uint4*)(Bs + r*SA_ + qq*8) =
            *(const uint4*)(g_W16 + (size_t)(cb + r)*E_ + qq*8);
    }
    __syncthreads();

    float c[4][4][4];
    #pragma unroll
    for (int mi = 0; mi < 4; ++mi)
        #pragma unroll
        for (int ni = 0; ni < 4; ++ni)
            #pragma unroll
            for (int qq = 0; qq < 4; ++qq) c[mi][ni][qq] = 0.f;

    #pragma unroll
    for (int kk = 0; kk < 8; ++kk) {
        const int k0 = kk * 16;
        uint32_t a[4][4];
        #pragma unroll
        for (int mi = 0; mi < 4; ++mi) {
            const __half* p = As + (wm*64 + mi*16 + gid)*SA_ + k0 + 2*tig;
            a[mi][0] = *(const uint32_t*)p;
            a[mi][1] = *(const uint32_t*)(p + 8*SA_);
            a[mi][2] = *(const uint32_t*)(p + 8);
            a[mi][3] = *(const uint32_t*)(p + 8*SA_ + 8);
        }
        #pragma unroll
        for (int ni = 0; ni < 4; ++ni) {
            const __half* p = Bs + (wn*32 + ni*8 + gid)*SA_ + k0 + 2*tig;
            uint32_t b0 = *(const uint32_t*)p;
            uint32_t b1 = *(const uint32_t*)(p + 8);
            #pragma unroll
            for (int mi = 0; mi < 4; ++mi)
                mma16816(c[mi][ni], a[mi], b0, b1);
        }
    }

    #pragma unroll
    for (int ni = 0; ni < 4; ++ni) {
        int col = cb + wn*32 + ni*8 + 2*tig;
        float2 bv = *(const float2*)(sb + col);
        #pragma unroll
        for (int mi = 0; mi < 4; ++mi) {
            int r0 = rb + wm*64 + mi*16 + gid;
            float2 v0 = { c[mi][ni][0] + bv.x, c[mi][ni][1] + bv.y };
            float2 v1 = { c[mi][ni][2] + bv.x, c[mi][ni][3] + bv.y };
            *(float2*)(out + (size_t)r0      *V_ + col) = v0;
            *(float2*)(out + (size_t)(r0 + 8)*V_ + col) = v1;
        }
    }
}

// ---------------- launch ----------------
extern "C" void kernel_launch(void* const* d_in, const int* in_sizes, int n_in,
                              void* d_out, int out_size)
{
    const int*   ids   = (const int*)  d_in[0];
    const float* emb   = (const float*)d_in[1];
    const float* Wx    = (const float*)d_in[2];
    const float* Wh    = (const float*)d_in[3];
    const float* alpha = (const float*)d_in[4];
    const float* beta1 = (const float*)d_in[5];
    const float* beta2 = (const float*)d_in[6];
    const float* bias  = (const float*)d_in[7];
    const float* wi    = (const float*)d_in[8];
    const float* wf    = (const float*)d_in[9];
    const float* wo    = (const float*)d_in[10];
    const float* sw    = (const float*)d_in[11];
    const float* sbias = (const float*)d_in[12];
    float*       out   = (float*)d_out;

    const int SMEM_GEMM = (64 + 64) * SA_ * 2;            // 34816
    const int SMEM_PROJ = 2 * 128 * SA_ * 2;              // 69632

    cudaFuncSetAttribute(k_gemm_xh, cudaFuncAttributeMaxDynamicSharedMemorySize, SMEM_GEMM);
    cudaFuncSetAttribute(k_proj,    cudaFuncAttributeMaxDynamicSharedMemorySize, SMEM_PROJ);

    k_embed<<<(BT_*E_/8 + 255)/256, 256>>>(ids, emb);
    k_wx2half<<<(L_*G_*E_ + 255)/256, 256>>>(Wx);
    k_w2half<<<(V_*E_ + 255)/256, 256>>>(sw);

    // layer 0
    k_gemm_xh<<<dim3(G_/64, BT_/64), 256, SMEM_GEMM>>>(0, 0);
    k_milstm<<<2*B_, 256>>>(Wh, alpha, beta1, beta2, bias, wi, wf, wo, 0);

    // layer 1
    k_gemm_xh<<<dim3(G_/64, BT_/64), 256, SMEM_GEMM>>>(1, 1);
    k_milstm<<<2*B_, 256>>>(Wh + E_*G_, alpha + G_, beta1 + G_, beta2 + G_,
                            bias + G_, wi + E_, wf + E_, wo + E_, 1);

    // projection (g_Ah written directly by layer-1 milstm)
    k_proj<<<dim3(V_/128, BT_/128), 256, SMEM_PROJ>>>(sbias, out);
}

// round 16
// speedup vs baseline: 1.2760x; 1.0165x over previous
#include <cuda_runtime.h>
#include <cuda_fp16.h>
#include <cstdint>
#include <math.h>

#define V_  32000
#define E_  128
#define L_  2
#define B_  32
#define T_  128
#define G_  512          // 4*E
#define BT_ (B_*T_)      // 4096

// ---------------- device scratch (no allocations allowed) ----------------
__device__ __half g_x16 [BT_*E_];   // embedded inputs, fp16
__device__ __half g_h016[BT_*E_];   // layer-0 hidden seq, fp16 (feeds L1 gemm)
__device__ __half g_Ah  [BT_*E_];   // layer-1 hidden seq, fp16 (feeds proj)
__device__ float  g_xh [BT_*G_];    // x @ Wx for current layer (8 MB)
__device__ __half g_Wx16[L_*G_*E_]; // fp16 Wx, PRE-TRANSPOSED to [G][E] per layer
__device__ __half g_W16 [V_*E_];    // fp16 copy of softmax_w (8 MB)

__device__ __forceinline__ uint32_t s2u(const void* p)
{
    uint32_t a;
    asm("{ .reg .u64 t; cvta.to.shared.u64 t, %1; cvt.u32.u64 %0, t; }"
        : "=r"(a) : "l"(p));
    return a;
}

// ---------------- fast transcendentals (ex2/rcp approx, rel err ~1e-6) ----
__device__ __forceinline__ float sigm(float x)
{
    float e; asm("ex2.approx.ftz.f32 %0, %1;" : "=f"(e) : "f"(-1.4426950408889634f * x));
    float r; asm("rcp.approx.ftz.f32 %0, %1;" : "=f"(r) : "f"(1.0f + e));
    return r;
}
__device__ __forceinline__ float ftanh(float x)
{
    x = fmaxf(x, -40.0f);          // guard ex2 overflow -> NaN
    float e; asm("ex2.approx.ftz.f32 %0, %1;" : "=f"(e) : "f"(-2.8853900817779268f * x));
    float r; asm("rcp.approx.ftz.f32 %0, %1;" : "=f"(r) : "f"(1.0f + e));
    return (1.0f - e) * r;
}

// ---------------- embedding gather (vectorized, emit fp16) ----------------
__global__ void k_embed(const int* __restrict__ ids, const float* __restrict__ emb)
{
    int idx = blockIdx.x * blockDim.x + threadIdx.x;   // over BT_*E_/8
    if (idx < BT_*E_/8) {
        int row = idx >> 4;           // b*T + t   (16 chunks of 8 per row)
        int q   = idx & 15;
        const float* src = emb + (size_t)ids[row]*E_ + q*8;
        float4 f0 = *(const float4*)(src);
        float4 f1 = *(const float4*)(src + 4);
        __half2 h[4];
        h[0] = __floats2half2_rn(f0.x, f0.y);
        h[1] = __floats2half2_rn(f0.z, f0.w);
        h[2] = __floats2half2_rn(f1.x, f1.y);
        h[3] = __floats2half2_rn(f1.z, f1.w);
        *(uint4*)(g_x16 + (size_t)row*E_ + q*8) = *(uint4*)h;
    }
}

// ---------------- fp32 -> fp16 weight converts ----------------
__global__ void k_w2half(const float* __restrict__ w)
{
    int idx = blockIdx.x * blockDim.x + threadIdx.x;
    if (idx < V_*E_) g_W16[idx] = __float2half(w[idx]);
}
// Wx [L][E][G] (k-major) -> g_Wx16 [L][G][E] (n-major, pre-transposed)
__global__ void k_wx2half(const float* __restrict__ wx)
{
    int idx = blockIdx.x * blockDim.x + threadIdx.x;
    if (idx < L_*G_*E_) {
        int l = idx / (G_*E_);
        int r = idx % (G_*E_);
        int g = r / E_;
        int e = r % E_;
        g_Wx16[idx] = __float2half(wx[(size_t)l*E_*G_ + (size_t)e*G_ + g]);
    }
}

// ---------------- HMMA helper ----------------
__device__ __forceinline__ void mma16816(float* c, const uint32_t* a,
                                         uint32_t b0, uint32_t b1)
{
    asm volatile(
        "mma.sync.aligned.m16n8k16.row.col.f32.f16.f16.f32 "
        "{%0,%1,%2,%3}, {%4,%5,%6,%7}, {%8,%9}, {%0,%1,%2,%3};\n"
        : "+f"(c[0]), "+f"(c[1]), "+f"(c[2]), "+f"(c[3])
        : "r"(a[0]), "r"(a[1]), "r"(a[2]), "r"(a[3]), "r"(b0), "r"(b1));
}

#define SA_ 136   // padded smem row in halves

// ---------------- xh GEMM (fp16 HMMA): (BT x E) @ (E x G) -> g_xh ----------------
__global__ void __launch_bounds__(256, 2)
k_gemm_xh(int layer, int src)
{
    const __half* A   = src ? g_h016 : g_x16;
    const __half* Wxt = g_Wx16 + (size_t)layer * G_ * E_;
    extern __shared__ __half gsm[];
    __half* As = gsm;              // [64][SA_]
    __half* Bs = gsm + 64*SA_;     // [64][SA_]  (n-major, k contiguous)

    const int tid  = threadIdx.x;
    const int wid  = tid >> 5, lane = tid & 31;
    const int gid  = lane >> 2, tig = lane & 3;
    const int wm   = wid >> 2, wn = wid & 3;      // 2 x 4 warps
    const int rb   = blockIdx.y * 64;
    const int nb   = blockIdx.x * 64;

    #pragma unroll
    for (int i = tid; i < 1024; i += 256) {
        int r = i >> 4, qq = i & 15;
        *(uint4*)(As + r*SA_ + qq*8) =
            *(const uint4*)(A + (size_t)(rb + r)*E_ + qq*8);
    }
    #pragma unroll
    for (int i = tid; i < 1024; i += 256) {
        int r = i >> 4, qq = i & 15;
        *(uint4*)(Bs + r*SA_ + qq*8) =
            *(const uint4*)(Wxt + (size_t)(nb + r)*E_ + qq*8);
    }
    __syncthreads();

    float c[2][2][4];
    #pragma unroll
    for (int mi = 0; mi < 2; ++mi)
        #pragma unroll
        for (int ni = 0; ni < 2; ++ni)
            #pragma unroll
            for (int qq = 0; qq < 4; ++qq) c[mi][ni][qq] = 0.f;

    #pragma unroll
    for (int kk = 0; kk < 8; ++kk) {
        const int k0 = kk * 16;
        uint32_t a[2][4];
        #pragma unroll
        for (int mi = 0; mi < 2; ++mi) {
            const __half* p = As + (wm*32 + mi*16 + gid)*SA_ + k0 + 2*tig;
            a[mi][0] = *(const uint32_t*)p;
            a[mi][1] = *(const uint32_t*)(p + 8*SA_);
            a[mi][2] = *(const uint32_t*)(p + 8);
            a[mi][3] = *(const uint32_t*)(p + 8*SA_ + 8);
        }
        #pragma unroll
        for (int ni = 0; ni < 2; ++ni) {
            const __half* p = Bs + (wn*16 + ni*8 + gid)*SA_ + k0 + 2*tig;
            uint32_t b0 = *(const uint32_t*)p;
            uint32_t b1 = *(const uint32_t*)(p + 8);
            #pragma unroll
            for (int mi = 0; mi < 2; ++mi)
                mma16816(c[mi][ni], a[mi], b0, b1);
        }
    }

    #pragma unroll
    for (int ni = 0; ni < 2; ++ni) {
        int col = nb + wn*16 + ni*8 + 2*tig;
        #pragma unroll
        for (int mi = 0; mi < 2; ++mi) {
            int r0 = rb + wm*32 + mi*16 + gid;
            *(float2*)(g_xh + (size_t)r0      *G_ + col) = make_float2(c[mi][ni][0], c[mi][ni][1]);
            *(float2*)(g_xh + (size_t)(r0 + 8)*G_ + col) = make_float2(c[mi][ni][2], c[mi][ni][3]);
        }
    }
}

// ---------------- miLSTM recurrence: 2-CTA cluster per batch element ----------------
// EXACT R15-proven version (83us per launch): st.async + double-buffered
// transaction mbarriers — data and completion in ONE DSMEM flight. Bounded
// waits. See R15 notes for the phase/causality argument.
__global__ void __launch_bounds__(256, 1) __cluster_dims__(2, 1, 1)
k_milstm(const float* __restrict__ Wh,
         const float* __restrict__ alpha,
         const float* __restrict__ beta1,
         const float* __restrict__ beta2,
         const float* __restrict__ bias,
         const float* __restrict__ wi,
         const float* __restrict__ wf,
         const float* __restrict__ wo,
         int layer)
{
    __shared__ float hbuf[2][128];                 // double-buffered hidden state
    __shared__ __align__(16) unsigned long long mbar[2];

    const int tid = threadIdx.x;
    uint32_t rank;
    asm("mov.u32 %0, %%cluster_ctarank;" : "=r"(rank));
    const int b = blockIdx.x >> 1;

    const int type = tid & 3;
    const int el   = tid >> 2;                     // 0..63
    const int gcol = type*128 + 64*(int)rank + el;

    float w[128];
    #pragma unroll
    for (int k = 0; k < 128; ++k)
        w[k] = Wh[(size_t)k*G_ + gcol];

    const float al = alpha[gcol], be1 = beta1[gcol], be2 = beta2[gcol], bi = bias[gcol];

    const int egl = 64*(int)rank + el;
    const float wie = wi[egl], wfe = wf[egl], woe = wo[egl];
    float cst = 0.f;

    const uint32_t b0_lo = s2u(&mbar[0]);
    const uint32_t b1_lo = s2u(&mbar[1]);
    if (tid < 128) { hbuf[0][tid] = 0.f; hbuf[1][tid] = 0.f; }
    if (tid == 0) {
        asm volatile("mbarrier.init.shared.b64 [%0], 1;" :: "r"(b0_lo) : "memory");
        asm volatile("mbarrier.init.shared.b64 [%0], 1;" :: "r"(b1_lo) : "memory");
        asm volatile("mbarrier.arrive.expect_tx.shared.b64 _, [%0], %1;" :: "r"(b0_lo), "r"(256) : "memory");
        asm volatile("mbarrier.arrive.expect_tx.shared.b64 _, [%0], %1;" :: "r"(b1_lo), "r"(256) : "memory");
    }
    __syncthreads();
    asm volatile("barrier.cluster.arrive.aligned;" ::: "memory");
    asm volatile("barrier.cluster.wait.aligned;"   ::: "memory");

    const uint32_t h_lo0 = s2u(&hbuf[0][0]);
    const uint32_t h_lo1 = s2u(&hbuf[1][0]);
    uint32_t b0_rm, b1_rm, h_rm0, h_rm1;
    {
        uint32_t peer = rank ^ 1u;
        asm("mapa.shared::cluster.u32 %0, %1, %2;" : "=r"(b0_rm) : "r"(b0_lo), "r"(peer));
        asm("mapa.shared::cluster.u32 %0, %1, %2;" : "=r"(b1_rm) : "r"(b1_lo), "r"(peer));
        asm("mapa.shared::cluster.u32 %0, %1, %2;" : "=r"(h_rm0) : "r"(h_lo0), "r"(peer));
        asm("mapa.shared::cluster.u32 %0, %1, %2;" : "=r"(h_rm1) : "r"(h_lo1), "r"(peer));
    }

    const float* xhb   = g_xh + (size_t)b * T_ * G_;
    __half*      houth = layer ? g_Ah : g_h016;

    float xv = xhb[gcol];
    uint32_t par0 = 0u, par1 = 0u;   // wait-parity per barrier

    for (int t = 0; t < T_; ++t) {
        int tn = (t + 1 < T_) ? (t + 1) : (T_ - 1);
        float xnext = xhb[(size_t)tn * G_ + gcol];   // prefetch next step's xh

        const float* hb = hbuf[t & 1];
        float s0 = 0.f, s1 = 0.f, s2 = 0.f, s3 = 0.f;

        // ---- own-slice half of the dot BEFORE the wait (hides peer flight)
        if (rank == 0) {
            #pragma unroll
            for (int k = 0; k < 64; k += 4) {
                float4 h4 = *(const float4*)(hb + k);
                s0 = __fmaf_rn(h4.x, w[k  ], s0);
                s1 = __fmaf_rn(h4.y, w[k+1], s1);
                s2 = __fmaf_rn(h4.z, w[k+2], s2);
                s3 = __fmaf_rn(h4.w, w[k+3], s3);
            }
        } else {
            #pragma unroll
            for (int k = 64; k < 128; k += 4) {
                float4 h4 = *(const float4*)(hb + k);
                s0 = __fmaf_rn(h4.x, w[k  ], s0);
                s1 = __fmaf_rn(h4.y, w[k+1], s1);
                s2 = __fmaf_rn(h4.z, w[k+2], s2);
                s3 = __fmaf_rn(h4.w, w[k+3], s3);
            }
        }

        // ---- wait for peer's h of the previous step (tx barrier, bounded)
        if (t > 0) {
            uint32_t blo = (t & 1) ? b1_lo : b0_lo;
            uint32_t p   = (t & 1) ? par1  : par0;
            uint32_t done;
            int spins = 0;
            do {
                asm volatile(
                    "{\n\t.reg .pred pp;\n\t"
                    "mbarrier.try_wait.parity.acquire.cluster.shared::cta.b64 pp, [%1], %2, 0x200;\n\t"
                    "selp.b32 %0, 1, 0, pp;\n\t}"
                    : "=r"(done) : "r"(blo), "r"(p) : "memory");
            } while (!done && ++spins < 65536);
            if (t & 1) par1 ^= 1u; else par0 ^= 1u;
            // re-arm this barrier for its use at step t+2 (before our sends)
            if (tid == 0)
                asm volatile("mbarrier.arrive.expect_tx.shared.b64 _, [%0], %1;"
                             :: "r"(blo), "r"(256) : "memory");
        }

        // ---- peer-slice half of the dot
        if (rank == 0) {
            #pragma unroll
            for (int k = 64; k < 128; k += 4) {
                float4 h4 = *(const float4*)(hb + k);
                s0 = __fmaf_rn(h4.x, w[k  ], s0);
                s1 = __fmaf_rn(h4.y, w[k+1], s1);
                s2 = __fmaf_rn(h4.z, w[k+2], s2);
                s3 = __fmaf_rn(h4.w, w[k+3], s3);
            }
        } else {
            #pragma unroll
            for (int k = 0; k < 64; k += 4) {
                float4 h4 = *(const float4*)(hb + k);
                s0 = __fmaf_rn(h4.x, w[k  ], s0);
                s1 = __fmaf_rn(h4.y, w[k+1], s1);
                s2 = __fmaf_rn(h4.z, w[k+2], s2);
                s3 = __fmaf_rn(h4.w, w[k+3], s3);
            }
        }
        float hh = (s0 + s1) + (s2 + s3);

        float g = xv * __fmaf_rn(al, hh, be1) + __fmaf_rn(be2, hh, bi);

        // gather i/j/f/o within the 4-lane group (independent shfls, overlap)
        float iv = __shfl_sync(0xffffffffu, g, 0, 4);
        float jv = __shfl_sync(0xffffffffu, g, 1, 4);
        float fv = __shfl_sync(0xffffffffu, g, 2, 4);
        float ov = __shfl_sync(0xffffffffu, g, 3, 4);

        iv += wie * cst;
        fv += wfe * cst;
        float cn = sigm(fv + 1.0f) * cst + sigm(iv) * ftanh(jv);
        ov += woe * cn;
        float hn = sigm(ov) * ftanh(cn);
        cst = cn;

        int nb = (t + 1) & 1;
        if (type == 0) {
            if (t < T_ - 1) {
                // data + tx-completion to peer in ONE flight
                uint32_t ra = (nb ? h_rm1 : h_rm0) + 4u * (uint32_t)egl;
                uint32_t rb = nb ? b1_rm : b0_rm;
                asm volatile(
                    "st.async.shared::cluster.mbarrier::complete_tx::bytes.b32 [%0], %1, [%2];"
                    :: "r"(ra), "r"(__float_as_uint(hn)), "r"(rb) : "memory");
            }
            hbuf[nb][egl] = hn;
            houth[((size_t)b * T_ + t) * E_ + egl] = __float2half(hn);
        }
        __syncthreads();   // local hbuf[nb] visible before next step's dot
        xv = xnext;
    }
}

// ---------------- projection: logits = h @ W^T + b  (fp16 HMMA) ----------------
// R10-proven structure (128x128 tile, 256 threads, 2 CTAs/SM) + R16 change:
// output stores are STREAMING (evict-first, __stcs) so the 524 MB write
// stream does not evict the L2-resident A (1 MB) / B (8 MB) operands — the
// re-reads stay L2 hits and DRAM traffic drops toward the ~533 MB compulsory
// minimum.
__global__ void __launch_bounds__(256, 2)
k_proj(const float* __restrict__ sb, float* __restrict__ out)
{
    extern __shared__ __half hsm[];
    __half* As = hsm;               // [128][SA_]
    __half* Bs = hsm + 128*SA_;     // [128][SA_]

    const int tid  = threadIdx.x;
    const int wid  = tid >> 5, lane = tid & 31;
    const int gid  = lane >> 2, tig = lane & 3;
    const int wm   = wid >> 2, wn = wid & 3;
    const int rb   = blockIdx.y * 128;
    const int cb   = blockIdx.x * 128;

    #pragma unroll
    for (int i = tid; i < 2048; i += 256) {
        int r = i >> 4, qq = i & 15;
        *(uint4*)(As + r*SA_ + qq*8) =
            *(const uint4*)(g_Ah + (size_t)(rb + r)*E_ + qq*8);
    }
    #pragma unroll
    for (int i = tid; i < 2048; i += 256) {
        int r = i >> 4, qq = i & 15;
        *(uint4*)(Bs + r*SA_ + qq*8) =
            *(const uint4*)(g_W16 + (size_t)(cb + r)*E_ + qq*8);
    }
    __syncthreads();

    float c[4][4][4];
    #pragma unroll
    for (int mi = 0; mi < 4; ++mi)
        #pragma unroll
        for (int ni = 0; ni < 4; ++ni)
            #pragma unroll
            for (int qq = 0; qq < 4; ++qq) c[mi][ni][qq] = 0.f;

    #pragma unroll
    for (int kk = 0; kk < 8; ++kk) {
        const int k0 = kk * 16;
        uint32_t a[4][4];
        #pragma unroll
        for (int mi = 0; mi < 4; ++mi) {
            const __half* p = As + (wm*64 + mi*16 + gid)*SA_ + k0 + 2*tig;
            a[mi][0] = *(const uint32_t*)p;
            a[mi][1] = *(const uint32_t*)(p + 8*SA_);
            a[mi][2] = *(const uint32_t*)(p + 8);
            a[mi][3] = *(const uint32_t*)(p + 8*SA_ + 8);
        }
        #pragma unroll
        for (int ni = 0; ni < 4; ++ni) {
            const __half* p = Bs + (wn*32 + ni*8 + gid)*SA_ + k0 + 2*tig;
            uint32_t b0 = *(const uint32_t*)p;
            uint32_t b1 = *(const uint32_t*)(p + 8);
            #pragma unroll
            for (int mi = 0; mi < 4; ++mi)
                mma16816(c[mi][ni], a[mi], b0, b1);
        }
    }

    #pragma unroll
    for (int ni = 0; ni < 4; ++ni) {
        int col = cb + wn*32 + ni*8 + 2*tig;
        float2 bv = *(const float2*)(sb + col);
        #pragma unroll
        for (int mi = 0; mi < 4; ++mi) {
            int r0 = rb + wm*64 + mi*16 + gid;
            float2 v0 = { c[mi][ni][0] + bv.x, c[mi][ni][1] + bv.y };
            float2 v1 = { c[mi][ni][2] + bv.x, c[mi][ni][3] + bv.y };
            __stcs((float2*)(out + (size_t)r0      *V_ + col), v0);
            __stcs((float2*)(out + (size_t)(r0 + 8)*V_ + col), v1);
        }
    }
}

// ---------------- launch ----------------
extern "C" void kernel_launch(void* const* d_in, const int* in_sizes, int n_in,
                              void* d_out, int out_size)
{
    const int*   ids   = (const int*)  d_in[0];
    const float* emb   = (const float*)d_in[1];
    const float* Wx    = (const float*)d_in[2];
    const float* Wh    = (const float*)d_in[3];
    const float* alpha = (const float*)d_in[4];
    const float* beta1 = (const float*)d_in[5];
    const float* beta2 = (const float*)d_in[6];
    const float* bias  = (const float*)d_in[7];
    const float* wi    = (const float*)d_in[8];
    const float* wf    = (const float*)d_in[9];
    const float* wo    = (const float*)d_in[10];
    const float* sw    = (const float*)d_in[11];
    const float* sbias = (const float*)d_in[12];
    float*       out   = (float*)d_out;

    const int SMEM_GEMM = (64 + 64) * SA_ * 2;            // 34816
    const int SMEM_PROJ = 2 * 128 * SA_ * 2;              // 69632

    cudaFuncSetAttribute(k_gemm_xh, cudaFuncAttributeMaxDynamicSharedMemorySize, SMEM_GEMM);
    cudaFuncSetAttribute(k_proj,    cudaFuncAttributeMaxDynamicSharedMemorySize, SMEM_PROJ);

    k_embed<<<(BT_*E_/8 + 255)/256, 256>>>(ids, emb);
    k_wx2half<<<(L_*G_*E_ + 255)/256, 256>>>(Wx);
    k_w2half<<<(V_*E_ + 255)/256, 256>>>(sw);

    // layer 0
    k_gemm_xh<<<dim3(G_/64, BT_/64), 256, SMEM_GEMM>>>(0, 0);
    k_milstm<<<2*B_, 256>>>(Wh, alpha, beta1, beta2, bias, wi, wf, wo, 0);

    // layer 1
    k_gemm_xh<<<dim3(G_/64, BT_/64), 256, SMEM_GEMM>>>(1, 1);
    k_milstm<<<2*B_, 256>>>(Wh + E_*G_, alpha + G_, beta1 + G_, beta2 + G_,
                            bias + G_, wi + E_, wf + E_, wo + E_, 1);

    // projection (g_Ah written directly by layer-1 milstm)
    k_proj<<<dim3(V_/128, BT_/128), 256, SMEM_PROJ>>>(sbias, out);
}